// round 11
// baseline (speedup 1.0000x reference)
#include <cuda_runtime.h>
#include <cuda_fp16.h>

typedef unsigned long long U64;

// ---------------- packed f32x2 helpers (Blackwell FFMA2, PTX-only) ----------------
__device__ __forceinline__ U64 pk2(float x, float y) {
    U64 r; asm("mov.b64 %0, {%1, %2};" : "=l"(r) : "f"(x), "f"(y)); return r;
}
__device__ __forceinline__ float lo2(U64 v) {
    float x; asm("{ .reg .f32 hi; mov.b64 {%0, hi}, %1; }" : "=f"(x) : "l"(v)); return x;
}
__device__ __forceinline__ float hi2(U64 v) {
    float y; asm("{ .reg .f32 lo; mov.b64 {lo, %0}, %1; }" : "=f"(y) : "l"(v)); return y;
}
__device__ __forceinline__ U64 fma2(U64 a, U64 b, U64 c) {
    U64 d; asm("fma.rn.f32x2 %0, %1, %2, %3;" : "=l"(d) : "l"(a), "l"(b), "l"(c)); return d;
}
__device__ __forceinline__ U64 add2(U64 a, U64 b) {
    U64 d; asm("add.rn.f32x2 %0, %1, %2;" : "=l"(d) : "l"(a), "l"(b)); return d;
}

// ---------------- fast transcendentals ----------------
__device__ __forceinline__ float rsqf(float x) { float r; asm("rsqrt.approx.f32 %0, %1;" : "=f"(r) : "f"(x)); return r; }
__device__ __forceinline__ float tanh_ap(float x) { float r; asm("tanh.approx.f32 %0, %1;" : "=f"(r) : "f"(x)); return r; }
__device__ __forceinline__ float sigm_ap(float v) {
    return fmaf(tanh_ap(0.5f * v), 0.5f, 0.5f);
}

static constexpr int Tn = 1000;
static constexpr int In = 13;
static constexpr int Hn = 13;
static constexpr int Bn = 2048;
static constexpr int W   = 64;     // warm-up steps per chunk
static constexpr int CH  = 500;    // output steps per chunk
static constexpr int NCH = 2;      // chunks (CH*NCH == Tn)
static constexpr int TP  = Tn + 2 * W;  // padded time dim (1128)
static constexpr long long OUT_ELEMS = (long long)Bn * Tn * 2 * Hn;  // 53,248,000
static constexpr long long HN_ELEMS  = 2LL * Bn * Hn;

// Scratch: gate preactivations (i,f,g,o) as half4 (uint2) per (tp,k),
// layout [d][b][tp][k] with tp = t + W; zero pads at tp<W and tp>=Tn+W.
// Zero g keeps (h,c)=(0,0) fixed -> warm-up across pads is exact. 480 MB.
__device__ uint2 g2h[2LL * Bn * TP * Hn];

// =====================================================================
// Pad kernel: zero both W-wide strips of every (d,b) plane.
// =====================================================================
__global__ void pad_kernel()
{
    const long long n = 2LL * Bn * W * Hn;
    const long long i = (long long)blockIdx.x * 256 + threadIdx.x;
    if (i < n) {
        const int k  = (int)(i % Hn);
        long long r  = i / Hn;
        const int tw = (int)(r % W); r /= W;
        const int b  = (int)(r % Bn);
        const int d  = (int)(r / Bn);
        const long long base = (((long long)d * Bn + b) * TP) * Hn + k;
        g2h[base + (long long)tw * Hn] = make_uint2(0u, 0u);
        g2h[base + (long long)(Tn + W + tw) * Hn] = make_uint2(0u, 0u);
    }
}

// =====================================================================
// Kernel A: x-path, one THREAD per (b, 2 timesteps). LayerNorm folded
// into weights: y = rs*(W'.x - mu*u) + v. Each weight LDS.64 feeds TWO
// fma2. Staged in smem; copied out linearly per dir plane at tp = t + W.
// =====================================================================
__global__ void __launch_bounds__(128, 2) xpre_kernel(
    const float* __restrict__ x,
    const float* __restrict__ ln_w, const float* __restrict__ ln_b,
    const float* __restrict__ wih_f, const float* __restrict__ bih_f, const float* __restrict__ bhh_f,
    const float* __restrict__ wih_b, const float* __restrict__ bih_b, const float* __restrict__ bhh_b)
{
    __shared__ __align__(8) uint2 ssm[256 * 13];   // 26.6 KB staging (one dir at a time)
    __shared__ __align__(8) float wsm[13][52][2];  // folded weights, pair layout
    __shared__ __align__(8) float usm[52][2];
    __shared__ __align__(8) float vsm[52][2];

    const int tid = threadIdx.x;

    if (tid < 104) {
        const int half    = tid & 1;
        const int pairIdx = tid >> 1;
        const int d       = pairIdx / 26;
        const int p       = pairIdx % 26;
        const int grp     = p / 13;
        const int k13     = p % 13;
        const int row     = grp * 26 + k13 + half * 13;
        const float* Wm = d ? wih_b : wih_f;
        const float* Bi = d ? bih_b : bih_f;
        const float* Bh = d ? bhh_b : bhh_f;
        float u = 0.0f;
        float v = __ldg(&Bi[row]) + __ldg(&Bh[row]);
#pragma unroll
        for (int j = 0; j < In; ++j) {
            const float wv = __ldg(&Wm[row * In + j]);
            const float wp = wv * __ldg(&ln_w[j]);
            wsm[j][pairIdx][half] = wp;
            u += wp;
            v = fmaf(wv, __ldg(&ln_b[j]), v);
        }
        usm[pairIdx][half] = u;
        vsm[pairIdx][half] = v;
    }
    __syncthreads();

    const int b  = blockIdx.y;
    const int t0 = blockIdx.x * 256;
    const int tA = t0 + tid;
    const int tB = tA + 128;
    const bool actA = (tA < Tn);
    const bool actB = (tB < Tn);
    const int nvalid = (Tn - t0 < 256) ? (Tn - t0) : 256;

    float xa[In], xb[In];
    float SA = 0.0f, S2A = 0.0f, SB = 0.0f, S2B = 0.0f;
    const float* xpA = x + ((long long)b * Tn + tA) * In;
    const float* xpB = x + ((long long)b * Tn + tB) * In;
#pragma unroll
    for (int j = 0; j < In; ++j) {
        xa[j] = actA ? __ldg(xpA + j) : 0.0f;
        xb[j] = actB ? __ldg(xpB + j) : 0.0f;
        SA += xa[j];  S2A = fmaf(xa[j], xa[j], S2A);
        SB += xb[j];  S2B = fmaf(xb[j], xb[j], S2B);
    }
    const float muA = SA * (1.0f / 13.0f);
    const float rsA = rsqf(fmaf(-muA, muA, S2A * (1.0f / 13.0f)) + 1e-5f);
    const float muB = SB * (1.0f / 13.0f);
    const float rsB = rsqf(fmaf(-muB, muB, S2B * (1.0f / 13.0f)) + 1e-5f);
    const U64 nmuA2 = pk2(-muA, -muA), rsA2 = pk2(rsA, rsA);
    const U64 nmuB2 = pk2(-muB, -muB), rsB2 = pk2(rsB, rsB);

#pragma unroll
    for (int d = 0; d < 2; ++d) {
        U64 accA[26], accB[26];
#pragma unroll
        for (int p = 0; p < 26; ++p) { accA[p] = 0ULL; accB[p] = 0ULL; }

        for (int j = 0; j < In; ++j) {
            const U64 xa2 = pk2(xa[j], xa[j]);
            const U64 xb2 = pk2(xb[j], xb[j]);
#pragma unroll
            for (int p = 0; p < 26; ++p) {
                const U64 wv = *(const U64*)&wsm[j][d * 26 + p][0];
                accA[p] = fma2(wv, xa2, accA[p]);
                accB[p] = fma2(wv, xb2, accB[p]);
            }
        }

#pragma unroll
        for (int p = 0; p < 13; ++p) {
            const U64 uIF = *(const U64*)&usm[d * 26 + p][0];
            const U64 vIF = *(const U64*)&vsm[d * 26 + p][0];
            const U64 uGO = *(const U64*)&usm[d * 26 + 13 + p][0];
            const U64 vGO = *(const U64*)&vsm[d * 26 + 13 + p][0];

            const U64 yAif = fma2(fma2(uIF, nmuA2, accA[p]),      rsA2, vIF);
            const U64 yAgo = fma2(fma2(uGO, nmuA2, accA[13 + p]), rsA2, vGO);
            const U64 yBif = fma2(fma2(uIF, nmuB2, accB[p]),      rsB2, vIF);
            const U64 yBgo = fma2(fma2(uGO, nmuB2, accB[13 + p]), rsB2, vGO);

            const __half2 hAif = __float22half2_rn(make_float2(lo2(yAif), hi2(yAif)));
            const __half2 hAgo = __float22half2_rn(make_float2(lo2(yAgo), hi2(yAgo)));
            const __half2 hBif = __float22half2_rn(make_float2(lo2(yBif), hi2(yBif)));
            const __half2 hBgo = __float22half2_rn(make_float2(lo2(yBgo), hi2(yBgo)));

            uint2 uA, uB;
            uA.x = *(const unsigned*)&hAif;  uA.y = *(const unsigned*)&hAgo;
            uB.x = *(const unsigned*)&hBif;  uB.y = *(const unsigned*)&hBgo;
            ssm[tid * 13 + p]         = uA;
            ssm[(tid + 128) * 13 + p] = uB;
        }
        __syncthreads();

        // Linear coalesced copy into dir plane d at tp = t + W
        uint2* dst = g2h + (((long long)d * Bn + b) * TP + (t0 + W)) * Hn;
        const int n = nvalid * 13;
        for (int i = tid; i < n; i += 128)
            dst[i] = ssm[i];
        __syncthreads();
    }
}

// =====================================================================
// Kernel B: chunked recurrence. One warp per (b, chunk): 4096 warps.
// Lanes 0-15 fwd, 16-31 bwd. Each chunk runs W warm-up steps from
// (h,c)=(0,0) (zero-pad region or real g for interior chunks), then CH
// output steps. Unguarded 4-deep prefetch (pads keep reads in-bounds).
// =====================================================================
__global__ void __launch_bounds__(64, 4) rec_kernel(
    const float* __restrict__ whh_f, const float* __restrict__ whh_b,
    float* __restrict__ out)
{
    __shared__ __align__(8) float2 hsm[2][2][2][14];  // [warp][buf][dir][pad 14]

    const int lane = threadIdx.x & 31;
    const int w    = threadIdx.x >> 5;
    const int gw   = blockIdx.x * 2 + w;    // 0..4095
    const int b    = gw & (Bn - 1);
    const int cc   = gw >> 11;              // chunk 0 or 1
    const int dir  = lane >> 4;
    const int k    = lane & 15;
    const bool active = (k < Hn);
    const int kk   = active ? k : 0;

    const float* Whh = dir ? whh_b : whh_f;

    U64 wif[In], wgo[In];
#pragma unroll
    for (int j = 0; j < In; ++j) {
        wif[j] = pk2(__ldg(&Whh[kk * Hn + j]),            __ldg(&Whh[(Hn + kk) * Hn + j]));
        wgo[j] = pk2(__ldg(&Whh[(2 * Hn + kk) * Hn + j]), __ldg(&Whh[(3 * Hn + kk) * Hn + j]));
    }

    if (active) {
        hsm[w][0][dir][k] = make_float2(0.0f, 0.0f);
        hsm[w][1][dir][k] = make_float2(0.0f, 0.0f);
    }
    __syncwarp();

    // g index (padded): fwd starts at tp = cc*CH (t = cc*CH - W);
    // bwd starts at tp = cc*CH + CH - 1 + 2W (t = cc*CH + CH - 1 + W).
    const int tp0 = dir ? (cc * CH + CH - 1 + 2 * W) : (cc * CH);
    const uint2* gp = g2h + (((long long)dir * Bn + b) * TP + tp0) * Hn + kk;
    const int dgp = dir ? -Hn : Hn;

    // out pointer at first written t
    const int tout0 = dir ? (cc * CH + CH - 1) : (cc * CH);
    float* op = out + ((long long)b * Tn + tout0) * (2 * Hn) + dir * Hn + kk;
    const int dop = dir ? -(2 * Hn) : (2 * Hn);

    float c = 0.0f, h = 0.0f;

    uint2 gb[4];
#pragma unroll
    for (int i = 0; i < 4; ++i) { gb[i] = __ldg(gp); gp += dgp; }

#pragma unroll 4
    for (int t = 0; t < W + CH; ++t) {
        const uint2 graw = gb[t & 3];
        gb[t & 3] = __ldg(gp); gp += dgp;   // unguarded: pads keep it in-bounds

        const float2 gxy = __half22float2(*(const __half2*)&graw.x);
        const float2 gzw = __half22float2(*(const __half2*)&graw.y);

        const int cur = t & 1, nxt = cur ^ 1;

        U64 aif0 = pk2(gxy.x, gxy.y), aif1 = 0ULL;
        U64 ago0 = pk2(gzw.x, gzw.y), ago1 = 0ULL;
#pragma unroll
        for (int j = 0; j < 12; j += 2) {
            const U64 h0 = *(const U64*)&hsm[w][cur][dir][j];
            const U64 h1 = *(const U64*)&hsm[w][cur][dir][j + 1];
            aif0 = fma2(wif[j],     h0, aif0);
            ago0 = fma2(wgo[j],     h0, ago0);
            aif1 = fma2(wif[j + 1], h1, aif1);
            ago1 = fma2(wgo[j + 1], h1, ago1);
        }
        {
            const U64 h12 = *(const U64*)&hsm[w][cur][dir][12];
            aif0 = fma2(wif[12], h12, aif0);
            ago0 = fma2(wgo[12], h12, ago0);
        }
        const U64 aif = add2(aif0, aif1);
        const U64 ago = add2(ago0, ago1);

        const float gi = sigm_ap(lo2(aif));
        const float gf = sigm_ap(hi2(aif));
        const float gg = tanh_ap(lo2(ago));
        const float go = sigm_ap(hi2(ago));

        c = fmaf(gf, c, gi * gg);
        h = go * tanh_ap(c);

        if (active) hsm[w][nxt][dir][k] = make_float2(h, h);
        if (t >= W) {
            if (active) *op = h;
            op += dop;
        }
        __syncwarp();
    }

    // Terminal states: fwd from last chunk, bwd from first chunk
    const bool terminal = dir ? (cc == 0) : (cc == NCH - 1);
    if (active && terminal) {
        float* hn = out + OUT_ELEMS + (long long)dir * (Bn * Hn) + (long long)b * Hn + k;
        hn[0] = h;
        hn[HN_ELEMS] = c;
    }
}

extern "C" void kernel_launch(void* const* d_in, const int* in_sizes, int n_in,
                              void* d_out, int out_size)
{
    const float* x     = (const float*)d_in[0];
    const float* ln_w  = (const float*)d_in[1];
    const float* ln_b  = (const float*)d_in[2];
    const float* wih_f = (const float*)d_in[3];
    const float* whh_f = (const float*)d_in[4];
    const float* bih_f = (const float*)d_in[5];
    const float* bhh_f = (const float*)d_in[6];
    const float* wih_b = (const float*)d_in[7];
    const float* whh_b = (const float*)d_in[8];
    const float* bih_b = (const float*)d_in[9];
    const float* bhh_b = (const float*)d_in[10];
    float* out = (float*)d_out;

    // Zero the warm-up pad strips (idempotent)
    const long long npad = 2LL * Bn * W * Hn;
    pad_kernel<<<(int)((npad + 255) / 256), 256>>>();

    // Kernel A: 2 timesteps per thread; grid (4, 2048)
    dim3 gridA((Tn + 255) / 256, Bn);
    xpre_kernel<<<gridA, 128>>>(x, ln_w, ln_b,
                                wih_f, bih_f, bhh_f,
                                wih_b, bih_b, bhh_b);

    // Kernel B: one warp per (b, chunk): 4096 warps, 2 per block
    rec_kernel<<<4096 / 2, 64>>>(whh_f, whh_b, out);
}

// round 13
// speedup vs baseline: 1.7088x; 1.7088x over previous
#include <cuda_runtime.h>
#include <cuda_fp16.h>

typedef unsigned long long U64;

// ---------------- packed f32x2 helpers (Blackwell FFMA2, PTX-only) ----------------
__device__ __forceinline__ U64 pk2(float x, float y) {
    U64 r; asm("mov.b64 %0, {%1, %2};" : "=l"(r) : "f"(x), "f"(y)); return r;
}
__device__ __forceinline__ float lo2(U64 v) {
    float x; asm("{ .reg .f32 hi; mov.b64 {%0, hi}, %1; }" : "=f"(x) : "l"(v)); return x;
}
__device__ __forceinline__ float hi2(U64 v) {
    float y; asm("{ .reg .f32 lo; mov.b64 {lo, %0}, %1; }" : "=f"(y) : "l"(v)); return y;
}
__device__ __forceinline__ U64 fma2(U64 a, U64 b, U64 c) {
    U64 d; asm("fma.rn.f32x2 %0, %1, %2, %3;" : "=l"(d) : "l"(a), "l"(b), "l"(c)); return d;
}

// ---------------- fast transcendentals ----------------
__device__ __forceinline__ float rsqf(float x) { float r; asm("rsqrt.approx.f32 %0, %1;" : "=f"(r) : "f"(x)); return r; }
__device__ __forceinline__ float tanh_ap(float x) { float r; asm("tanh.approx.f32 %0, %1;" : "=f"(r) : "f"(x)); return r; }
__device__ __forceinline__ float sigm_ap(float v) {
    return fmaf(tanh_ap(0.5f * v), 0.5f, 0.5f);
}

static constexpr int Tn = 1000;
static constexpr int In = 13;
static constexpr int Hn = 13;
static constexpr int Bn = 2048;
static constexpr long long OUT_ELEMS = (long long)Bn * Tn * 2 * Hn;  // 53,248,000
static constexpr long long HN_ELEMS  = 2LL * Bn * Hn;

// Scratch: gate preactivations (i,f,g,o) as half4 (uint2) per (t,k),
// dir-major [d][b][t][k].  426 MB.
__device__ uint2 g2h[2LL * Bn * Tn * Hn];

// =====================================================================
// Kernel A (exact R10 form, proven ~185us): one THREAD per (b, 2 t's).
// LayerNorm folded into weights: y = rs*(W'.x - mu*u) + v; each weight
// LDS.64 feeds two fma2; staged in smem; linear coalesced copy-out.
// =====================================================================
__global__ void __launch_bounds__(128, 2) xpre_kernel(
    const float* __restrict__ x,
    const float* __restrict__ ln_w, const float* __restrict__ ln_b,
    const float* __restrict__ wih_f, const float* __restrict__ bih_f, const float* __restrict__ bhh_f,
    const float* __restrict__ wih_b, const float* __restrict__ bih_b, const float* __restrict__ bhh_b)
{
    __shared__ __align__(8) uint2 ssm[256 * 13];
    __shared__ __align__(8) float wsm[13][52][2];
    __shared__ __align__(8) float usm[52][2];
    __shared__ __align__(8) float vsm[52][2];

    const int tid = threadIdx.x;

    if (tid < 104) {
        const int half    = tid & 1;
        const int pairIdx = tid >> 1;
        const int d       = pairIdx / 26;
        const int p       = pairIdx % 26;
        const int grp     = p / 13;
        const int k13     = p % 13;
        const int row     = grp * 26 + k13 + half * 13;
        const float* Wm = d ? wih_b : wih_f;
        const float* Bi = d ? bih_b : bih_f;
        const float* Bh = d ? bhh_b : bhh_f;
        float u = 0.0f;
        float v = __ldg(&Bi[row]) + __ldg(&Bh[row]);
#pragma unroll
        for (int j = 0; j < In; ++j) {
            const float wv = __ldg(&Wm[row * In + j]);
            const float wp = wv * __ldg(&ln_w[j]);
            wsm[j][pairIdx][half] = wp;
            u += wp;
            v = fmaf(wv, __ldg(&ln_b[j]), v);
        }
        usm[pairIdx][half] = u;
        vsm[pairIdx][half] = v;
    }
    __syncthreads();

    const int b  = blockIdx.y;
    const int t0 = blockIdx.x * 256;
    const int tA = t0 + tid;
    const int tB = tA + 128;
    const bool actA = (tA < Tn);
    const bool actB = (tB < Tn);
    const int nvalid = (Tn - t0 < 256) ? (Tn - t0) : 256;

    float xa[In], xb[In];
    float SA = 0.0f, S2A = 0.0f, SB = 0.0f, S2B = 0.0f;
    const float* xpA = x + ((long long)b * Tn + tA) * In;
    const float* xpB = x + ((long long)b * Tn + tB) * In;
#pragma unroll
    for (int j = 0; j < In; ++j) {
        xa[j] = actA ? __ldg(xpA + j) : 0.0f;
        xb[j] = actB ? __ldg(xpB + j) : 0.0f;
        SA += xa[j];  S2A = fmaf(xa[j], xa[j], S2A);
        SB += xb[j];  S2B = fmaf(xb[j], xb[j], S2B);
    }
    const float muA = SA * (1.0f / 13.0f);
    const float rsA = rsqf(fmaf(-muA, muA, S2A * (1.0f / 13.0f)) + 1e-5f);
    const float muB = SB * (1.0f / 13.0f);
    const float rsB = rsqf(fmaf(-muB, muB, S2B * (1.0f / 13.0f)) + 1e-5f);
    const U64 nmuA2 = pk2(-muA, -muA), rsA2 = pk2(rsA, rsA);
    const U64 nmuB2 = pk2(-muB, -muB), rsB2 = pk2(rsB, rsB);

#pragma unroll
    for (int d = 0; d < 2; ++d) {
        U64 accA[26], accB[26];
#pragma unroll
        for (int p = 0; p < 26; ++p) { accA[p] = 0ULL; accB[p] = 0ULL; }

        for (int j = 0; j < In; ++j) {
            const U64 xa2 = pk2(xa[j], xa[j]);
            const U64 xb2 = pk2(xb[j], xb[j]);
#pragma unroll
            for (int p = 0; p < 26; ++p) {
                const U64 wv = *(const U64*)&wsm[j][d * 26 + p][0];
                accA[p] = fma2(wv, xa2, accA[p]);
                accB[p] = fma2(wv, xb2, accB[p]);
            }
        }

#pragma unroll
        for (int p = 0; p < 13; ++p) {
            const U64 uIF = *(const U64*)&usm[d * 26 + p][0];
            const U64 vIF = *(const U64*)&vsm[d * 26 + p][0];
            const U64 uGO = *(const U64*)&usm[d * 26 + 13 + p][0];
            const U64 vGO = *(const U64*)&vsm[d * 26 + 13 + p][0];

            const U64 yAif = fma2(fma2(uIF, nmuA2, accA[p]),      rsA2, vIF);
            const U64 yAgo = fma2(fma2(uGO, nmuA2, accA[13 + p]), rsA2, vGO);
            const U64 yBif = fma2(fma2(uIF, nmuB2, accB[p]),      rsB2, vIF);
            const U64 yBgo = fma2(fma2(uGO, nmuB2, accB[13 + p]), rsB2, vGO);

            const __half2 hAif = __float22half2_rn(make_float2(lo2(yAif), hi2(yAif)));
            const __half2 hAgo = __float22half2_rn(make_float2(lo2(yAgo), hi2(yAgo)));
            const __half2 hBif = __float22half2_rn(make_float2(lo2(yBif), hi2(yBif)));
            const __half2 hBgo = __float22half2_rn(make_float2(lo2(yBgo), hi2(yBgo)));

            uint2 uA, uB;
            uA.x = *(const unsigned*)&hAif;  uA.y = *(const unsigned*)&hAgo;
            uB.x = *(const unsigned*)&hBif;  uB.y = *(const unsigned*)&hBgo;
            ssm[tid * 13 + p]         = uA;
            ssm[(tid + 128) * 13 + p] = uB;
        }
        __syncthreads();

        uint2* dst = g2h + (((long long)d * Bn + b) * Tn + t0) * Hn;
        const int n = nvalid * 13;
        for (int i = tid; i < n; i += 128)
            dst[i] = ssm[i];
        __syncthreads();
    }
}

// =====================================================================
// Kernel B: recurrence, wavefront-minimized step. One warp per b;
// lanes 0-15 fwd, 16-31 bwd. h stored ONCE per slot in
// hsm[warp][buf][dir][14] (per-dir 56B rows -> each of the 7 j-pair
// LDS.64 loads touches 2 uniform addresses in one 128B line: 1 wavefront).
// Weights j-paired per gate row: 4 independent fma2 chains (7 deep) +
// 4 horizontal adds. 4-deep LDG prefetch; tanh.approx activations.
// =====================================================================
__global__ void __launch_bounds__(64, 7) rec_kernel(
    const float* __restrict__ whh_f, const float* __restrict__ whh_b,
    float* __restrict__ out)
{
    // [warp][buf][dir][14 floats]; slot 13 stays 0 (pad for j-pair 6)
    __shared__ __align__(8) float hsm[2][2][2][14];

    const int lane = threadIdx.x & 31;
    const int w    = threadIdx.x >> 5;
    const int dir  = lane >> 4;
    const int k    = lane & 15;
    const bool active = (k < Hn);
    const int kk   = active ? k : 0;
    const int b    = blockIdx.x * 2 + w;

    const float* Whh = dir ? whh_b : whh_f;

    // j-paired weights for this lane's 4 gate rows (i,f,g,o of hidden kk)
    U64 wi[7], wf_[7], wg[7], wo[7];
#pragma unroll
    for (int jj = 0; jj < 7; ++jj) {
        const int j0 = 2 * jj, j1 = 2 * jj + 1;
        const float i0 = __ldg(&Whh[kk * Hn + j0]);
        const float f0 = __ldg(&Whh[(Hn + kk) * Hn + j0]);
        const float g0 = __ldg(&Whh[(2 * Hn + kk) * Hn + j0]);
        const float o0 = __ldg(&Whh[(3 * Hn + kk) * Hn + j0]);
        const float i1 = (j1 < Hn) ? __ldg(&Whh[kk * Hn + j1]) : 0.0f;
        const float f1 = (j1 < Hn) ? __ldg(&Whh[(Hn + kk) * Hn + j1]) : 0.0f;
        const float g1 = (j1 < Hn) ? __ldg(&Whh[(2 * Hn + kk) * Hn + j1]) : 0.0f;
        const float o1 = (j1 < Hn) ? __ldg(&Whh[(3 * Hn + kk) * Hn + j1]) : 0.0f;
        wi[jj]  = pk2(i0, i1);
        wf_[jj] = pk2(f0, f1);
        wg[jj]  = pk2(g0, g1);
        wo[jj]  = pk2(o0, o1);
    }

    // Zero this warp's h buffer: 2 bufs x 2 dirs x 14 = 56 floats (incl. pads)
    {
        float* z = &hsm[w][0][0][0];
        for (int i = lane; i < 56; i += 32) z[i] = 0.0f;
    }
    __syncwarp();

    // g2h layout [d][b][t][k]
    const uint2* gp = g2h + (((long long)dir * Bn + b) * Tn + (dir ? Tn - 1 : 0)) * Hn + kk;
    const int dgp = dir ? -Hn : Hn;

    float* op = out + (long long)b * (Tn * 2 * Hn)
                    + (dir ? (long long)(Tn - 1) * 2 * Hn : 0) + dir * Hn + kk;
    const int dop = dir ? -(2 * Hn) : (2 * Hn);

    float c = 0.0f, h = 0.0f;

    uint2 gb[4];
#pragma unroll
    for (int i = 0; i < 4; ++i) { gb[i] = __ldg(gp); gp += dgp; }

#pragma unroll 4
    for (int t = 0; t < Tn; ++t) {
        const uint2 graw = gb[t & 3];
        if (t + 4 < Tn) { gb[t & 3] = __ldg(gp); gp += dgp; }

        const float2 gif = __half22float2(*(const __half2*)&graw.x);  // (i,f) preact
        const float2 ggo = __half22float2(*(const __half2*)&graw.y);  // (g,o) preact

        const int cur = t & 1, nxt = cur ^ 1;

        // 4 independent 7-deep fma2 chains sharing the 7 LDS.64 h-pair loads
        U64 ai = pk2(gif.x, 0.0f), af = pk2(gif.y, 0.0f);
        U64 ag = pk2(ggo.x, 0.0f), ao = pk2(ggo.y, 0.0f);
#pragma unroll
        for (int jj = 0; jj < 7; ++jj) {
            const U64 hp = *(const U64*)&hsm[w][cur][dir][2 * jj];   // 1 wavefront
            ai = fma2(wi[jj],  hp, ai);
            af = fma2(wf_[jj], hp, af);
            ag = fma2(wg[jj],  hp, ag);
            ao = fma2(wo[jj],  hp, ao);
        }

        const float gi = sigm_ap(lo2(ai) + hi2(ai));
        const float gf = sigm_ap(lo2(af) + hi2(af));
        const float gg = tanh_ap(lo2(ag) + hi2(ag));
        const float go = sigm_ap(lo2(ao) + hi2(ao));

        c = fmaf(gf, c, gi * gg);
        h = go * tanh_ap(c);

        if (active) {
            hsm[w][nxt][dir][k] = h;   // single copy, STS.32, 1 wavefront
            *op = h;
        }
        op += dop;
        __syncwarp();
    }

    if (active) {
        float* hn = out + OUT_ELEMS + (long long)dir * (Bn * Hn) + (long long)b * Hn + k;
        hn[0] = h;
        hn[HN_ELEMS] = c;
    }
}

extern "C" void kernel_launch(void* const* d_in, const int* in_sizes, int n_in,
                              void* d_out, int out_size)
{
    const float* x     = (const float*)d_in[0];
    const float* ln_w  = (const float*)d_in[1];
    const float* ln_b  = (const float*)d_in[2];
    const float* wih_f = (const float*)d_in[3];
    const float* whh_f = (const float*)d_in[4];
    const float* bih_f = (const float*)d_in[5];
    const float* bhh_f = (const float*)d_in[6];
    const float* wih_b = (const float*)d_in[7];
    const float* whh_b = (const float*)d_in[8];
    const float* bih_b = (const float*)d_in[9];
    const float* bhh_b = (const float*)d_in[10];
    float* out = (float*)d_out;

    // Kernel A: 2 timesteps per thread; grid (4, 2048)
    dim3 gridA((Tn + 255) / 256, Bn);
    xpre_kernel<<<gridA, 128>>>(x, ln_w, ln_b,
                                wih_f, bih_f, bhh_f,
                                wih_b, bih_b, bhh_b);

    // Kernel B: one warp per batch row, 2 warps/block
    rec_kernel<<<Bn / 2, 64>>>(whh_f, whh_b, out);
}

// round 14
// speedup vs baseline: 1.8615x; 1.0894x over previous
#include <cuda_runtime.h>
#include <cuda_fp16.h>

typedef unsigned long long U64;

// ---------------- packed f32x2 helpers (Blackwell FFMA2, PTX-only) ----------------
__device__ __forceinline__ U64 pk2(float x, float y) {
    U64 r; asm("mov.b64 %0, {%1, %2};" : "=l"(r) : "f"(x), "f"(y)); return r;
}
__device__ __forceinline__ float lo2(U64 v) {
    float x; asm("{ .reg .f32 hi; mov.b64 {%0, hi}, %1; }" : "=f"(x) : "l"(v)); return x;
}
__device__ __forceinline__ float hi2(U64 v) {
    float y; asm("{ .reg .f32 lo; mov.b64 {lo, %0}, %1; }" : "=f"(y) : "l"(v)); return y;
}
__device__ __forceinline__ U64 fma2(U64 a, U64 b, U64 c) {
    U64 d; asm("fma.rn.f32x2 %0, %1, %2, %3;" : "=l"(d) : "l"(a), "l"(b), "l"(c)); return d;
}
__device__ __forceinline__ U64 add2(U64 a, U64 b) {
    U64 d; asm("add.rn.f32x2 %0, %1, %2;" : "=l"(d) : "l"(a), "l"(b)); return d;
}

// ---------------- fast transcendentals ----------------
__device__ __forceinline__ float rsqf(float x) { float r; asm("rsqrt.approx.f32 %0, %1;" : "=f"(r) : "f"(x)); return r; }
__device__ __forceinline__ float tanh_ap(float x) { float r; asm("tanh.approx.f32 %0, %1;" : "=f"(r) : "f"(x)); return r; }
__device__ __forceinline__ float sigm_ap(float v) {
    return fmaf(tanh_ap(0.5f * v), 0.5f, 0.5f);
}

static constexpr int Tn = 1000;
static constexpr int In = 13;
static constexpr int Hn = 13;
static constexpr int Bn = 2048;
static constexpr long long OUT_ELEMS = (long long)Bn * Tn * 2 * Hn;  // 53,248,000
static constexpr long long HN_ELEMS  = 2LL * Bn * Hn;

// Scratch: gate preactivations (i,f,g,o) as half4 (uint2) per (t,k),
// dir-major [d][b][t][k].  426 MB.
__device__ uint2 g2h[2LL * Bn * Tn * Hn];

// =====================================================================
// Kernel A: x-path, one THREAD per (b, 2 t's). LayerNorm folded into
// weights: y = rs*(W'.x - mu*u) + v.  Accumulators split into two
// 13-pair groups processed sequentially -> live regs ~105 (was ~170),
// enabling 4 blocks/SM (16 warps) at ZERO extra weight-LDS cost.
// Staged as unsigned half2 slots; linear coalesced uint2 copy-out.
// =====================================================================
__global__ void __launch_bounds__(128, 4) xpre_kernel(
    const float* __restrict__ x,
    const float* __restrict__ ln_w, const float* __restrict__ ln_b,
    const float* __restrict__ wih_f, const float* __restrict__ bih_f, const float* __restrict__ bhh_f,
    const float* __restrict__ wih_b, const float* __restrict__ bih_b, const float* __restrict__ bhh_b)
{
    __shared__ __align__(8) unsigned ssm[256 * 26];    // 26.6 KB staging
    __shared__ __align__(8) float wsm[13][52][2];      // folded weights, pair layout
    __shared__ __align__(8) float usm[52][2];
    __shared__ __align__(8) float vsm[52][2];

    const int tid = threadIdx.x;

    // Prologue: 104 threads build folded-weight tables.
    // pairIdx: [0,26) dir0, [26,52) dir1; within dir: p<13 -> (i,f) of k=p,
    // p>=13 -> (g,o) of k=p-13.
    if (tid < 104) {
        const int half    = tid & 1;
        const int pairIdx = tid >> 1;
        const int d       = pairIdx / 26;
        const int p       = pairIdx % 26;
        const int grp     = p / 13;
        const int k13     = p % 13;
        const int row     = grp * 26 + k13 + half * 13;
        const float* Wm = d ? wih_b : wih_f;
        const float* Bi = d ? bih_b : bih_f;
        const float* Bh = d ? bhh_b : bhh_f;
        float u = 0.0f;
        float v = __ldg(&Bi[row]) + __ldg(&Bh[row]);
#pragma unroll
        for (int j = 0; j < In; ++j) {
            const float wv = __ldg(&Wm[row * In + j]);
            const float wp = wv * __ldg(&ln_w[j]);
            wsm[j][pairIdx][half] = wp;
            u += wp;
            v = fmaf(wv, __ldg(&ln_b[j]), v);
        }
        usm[pairIdx][half] = u;
        vsm[pairIdx][half] = v;
    }
    __syncthreads();

    const int b  = blockIdx.y;
    const int t0 = blockIdx.x * 256;
    const int tA = t0 + tid;
    const int tB = tA + 128;
    const bool actA = (tA < Tn);
    const bool actB = (tB < Tn);
    const int nvalid = (Tn - t0 < 256) ? (Tn - t0) : 256;

    // Load both x rows; local LN stats per row (no reduction)
    float xa[In], xb[In];
    float SA = 0.0f, S2A = 0.0f, SB = 0.0f, S2B = 0.0f;
    const float* xpA = x + ((long long)b * Tn + tA) * In;
    const float* xpB = x + ((long long)b * Tn + tB) * In;
#pragma unroll
    for (int j = 0; j < In; ++j) {
        xa[j] = actA ? __ldg(xpA + j) : 0.0f;
        xb[j] = actB ? __ldg(xpB + j) : 0.0f;
        SA += xa[j];  S2A = fmaf(xa[j], xa[j], S2A);
        SB += xb[j];  S2B = fmaf(xb[j], xb[j], S2B);
    }
    const float muA = SA * (1.0f / 13.0f);
    const float rsA = rsqf(fmaf(-muA, muA, S2A * (1.0f / 13.0f)) + 1e-5f);
    const float muB = SB * (1.0f / 13.0f);
    const float rsB = rsqf(fmaf(-muB, muB, S2B * (1.0f / 13.0f)) + 1e-5f);
    const U64 nmuA2 = pk2(-muA, -muA), rsA2 = pk2(rsA, rsA);
    const U64 nmuB2 = pk2(-muB, -muB), rsB2 = pk2(rsB, rsB);

    // 4 passes: (dir d, group g) with g=0 -> (i,f) pairs, g=1 -> (g,o) pairs.
    // Only 13+13 U64 accumulators live at a time.
#pragma unroll
    for (int d = 0; d < 2; ++d) {
#pragma unroll
        for (int g = 0; g < 2; ++g) {
            const int base = d * 26 + g * 13;
            U64 accA[13], accB[13];
#pragma unroll
            for (int p = 0; p < 13; ++p) { accA[p] = 0ULL; accB[p] = 0ULL; }

            for (int j = 0; j < In; ++j) {         // rolled: small I-footprint
                const U64 xa2 = pk2(xa[j], xa[j]);
                const U64 xb2 = pk2(xb[j], xb[j]);
#pragma unroll
                for (int p = 0; p < 13; ++p) {
                    const U64 wv = *(const U64*)&wsm[j][base + p][0];
                    accA[p] = fma2(wv, xa2, accA[p]);
                    accB[p] = fma2(wv, xb2, accB[p]);
                }
            }

            // Epilogue: finish LN affine; one half2 per (t,k) per group.
#pragma unroll
            for (int p = 0; p < 13; ++p) {
                const U64 uu = *(const U64*)&usm[base + p][0];
                const U64 vv = *(const U64*)&vsm[base + p][0];
                const U64 yA = fma2(fma2(uu, nmuA2, accA[p]), rsA2, vv);
                const U64 yB = fma2(fma2(uu, nmuB2, accB[p]), rsB2, vv);
                const __half2 hA = __float22half2_rn(make_float2(lo2(yA), hi2(yA)));
                const __half2 hB = __float22half2_rn(make_float2(lo2(yB), hi2(yB)));
                // slot layout: unsigned index 2*(t_local*13 + k) + g matches
                // uint2 element (t_local*13 + k) with .x = IF half2, .y = GO half2
                ssm[2 * (tid * 13 + p) + g]         = *(const unsigned*)&hA;
                ssm[2 * ((tid + 128) * 13 + p) + g] = *(const unsigned*)&hB;
            }
        }

        __syncthreads();

        // Linear coalesced copy into dir plane d ([d][b][t][k] uint2)
        uint2* dst = g2h + (((long long)d * Bn + b) * Tn + t0) * Hn;
        const uint2* src = (const uint2*)ssm;
        const int n = nvalid * 13;
        for (int i = tid; i < n; i += 128)
            dst[i] = src[i];
        __syncthreads();   // before ssm reuse by d=1
    }
}

// =====================================================================
// Kernel B: recurrence (exact R8/R10 known-good body, 298us). One warp
// per batch row; lanes 0-15 fwd, 16-31 bwd. 4-deep LDG.64 prefetch on
// fp16 gate preacts. h DUPLICATED (h,h) in smem; dual accumulators;
// tanh.approx activations. g scratch dir-major [d][b][t][k].
// =====================================================================
__global__ void __launch_bounds__(64, 7) rec_kernel(
    const float* __restrict__ whh_f, const float* __restrict__ whh_b,
    float* __restrict__ out)
{
    __shared__ __align__(8) float2 hsm[2][2][2][14];  // [warp][buf][dir][pad 14]

    const int lane = threadIdx.x & 31;
    const int w    = threadIdx.x >> 5;
    const int dir  = lane >> 4;
    const int k    = lane & 15;
    const bool active = (k < Hn);
    const int kk   = active ? k : 0;
    const int b    = blockIdx.x * 2 + w;

    const float* Whh = dir ? whh_b : whh_f;

    U64 wif[In], wgo[In];
#pragma unroll
    for (int j = 0; j < In; ++j) {
        wif[j] = pk2(__ldg(&Whh[kk * Hn + j]),            __ldg(&Whh[(Hn + kk) * Hn + j]));
        wgo[j] = pk2(__ldg(&Whh[(2 * Hn + kk) * Hn + j]), __ldg(&Whh[(3 * Hn + kk) * Hn + j]));
    }

    if (active) {
        hsm[w][0][dir][k] = make_float2(0.0f, 0.0f);
        hsm[w][1][dir][k] = make_float2(0.0f, 0.0f);
    }
    __syncwarp();

    // g2h layout [d][b][t][k]
    const uint2* gp = g2h + (((long long)dir * Bn + b) * Tn + (dir ? Tn - 1 : 0)) * Hn + kk;
    const int dgp = dir ? -Hn : Hn;

    float* op = out + (long long)b * (Tn * 2 * Hn)
                    + (dir ? (long long)(Tn - 1) * 2 * Hn : 0) + dir * Hn + kk;
    const int dop = dir ? -(2 * Hn) : (2 * Hn);

    float c = 0.0f, h = 0.0f;

    uint2 gb[4];
#pragma unroll
    for (int i = 0; i < 4; ++i) { gb[i] = __ldg(gp); gp += dgp; }

#pragma unroll 4
    for (int t = 0; t < Tn; ++t) {
        const uint2 graw = gb[t & 3];
        if (t + 4 < Tn) { gb[t & 3] = __ldg(gp); gp += dgp; }

        // fp16 -> fp32 (independent, hidden by pipeline)
        const float2 gxy = __half22float2(*(const __half2*)&graw.x);
        const float2 gzw = __half22float2(*(const __half2*)&graw.y);

        const int cur = t & 1, nxt = cur ^ 1;

        U64 aif0 = pk2(gxy.x, gxy.y), aif1 = 0ULL;
        U64 ago0 = pk2(gzw.x, gzw.y), ago1 = 0ULL;
#pragma unroll
        for (int j = 0; j < 12; j += 2) {
            const U64 h0 = *(const U64*)&hsm[w][cur][dir][j];
            const U64 h1 = *(const U64*)&hsm[w][cur][dir][j + 1];
            aif0 = fma2(wif[j],     h0, aif0);
            ago0 = fma2(wgo[j],     h0, ago0);
            aif1 = fma2(wif[j + 1], h1, aif1);
            ago1 = fma2(wgo[j + 1], h1, ago1);
        }
        {
            const U64 h12 = *(const U64*)&hsm[w][cur][dir][12];
            aif0 = fma2(wif[12], h12, aif0);
            ago0 = fma2(wgo[12], h12, ago0);
        }
        const U64 aif = add2(aif0, aif1);
        const U64 ago = add2(ago0, ago1);

        const float gi = sigm_ap(lo2(aif));
        const float gf = sigm_ap(hi2(aif));
        const float gg = tanh_ap(lo2(ago));
        const float go = sigm_ap(hi2(ago));

        c = fmaf(gf, c, gi * gg);
        h = go * tanh_ap(c);

        if (active) { hsm[w][nxt][dir][k] = make_float2(h, h); *op = h; }
        op += dop;
        __syncwarp();
    }

    if (active) {
        float* hn = out + OUT_ELEMS + (long long)dir * (Bn * Hn) + (long long)b * Hn + k;
        hn[0] = h;
        hn[HN_ELEMS] = c;
    }
}

extern "C" void kernel_launch(void* const* d_in, const int* in_sizes, int n_in,
                              void* d_out, int out_size)
{
    const float* x     = (const float*)d_in[0];
    const float* ln_w  = (const float*)d_in[1];
    const float* ln_b  = (const float*)d_in[2];
    const float* wih_f = (const float*)d_in[3];
    const float* whh_f = (const float*)d_in[4];
    const float* bih_f = (const float*)d_in[5];
    const float* bhh_f = (const float*)d_in[6];
    const float* wih_b = (const float*)d_in[7];
    const float* whh_b = (const float*)d_in[8];
    const float* bih_b = (const float*)d_in[9];
    const float* bhh_b = (const float*)d_in[10];
    float* out = (float*)d_out;

    // Kernel A: 2 timesteps per thread; grid (4, 2048)
    dim3 gridA((Tn + 255) / 256, Bn);
    xpre_kernel<<<gridA, 128>>>(x, ln_w, ln_b,
                                wih_f, bih_f, bhh_f,
                                wih_b, bih_b, bhh_b);

    // Kernel B: one warp per batch row, 2 warps/block
    rec_kernel<<<Bn / 2, 64>>>(whh_f, whh_b, out);
}